// round 1
// baseline (speedup 1.0000x reference)
#include <cuda_runtime.h>
#include <math.h>
#include <stdint.h>

// ---------------- problem constants ----------------
#define T_STEPS 600
#define BATCH   64
#define HID     40
#define IN_F    257
#define NTOK    (BATCH * T_STEPS)   // 38400
#define G3H     120                 // 3*HID
#define KEXP    720                 // 80 silu + 80*8 spline bases
#define TWOH    80

// ---------------- scratch (static device memory; no allocations) ----------------
__device__ float g_giF[(size_t)T_STEPS * BATCH * G3H];   // layer-0 fwd input gates, (t,b,120)
__device__ float g_giB[(size_t)T_STEPS * BATCH * G3H];   // layer-0 bwd input gates, (t,b,120)
__device__ float g_hcat[(size_t)NTOK * TWOH];            // (b,t,80) concat fwd|bwd top-layer h
__device__ float g_feat[(size_t)NTOK * KEXP];            // expanded KAN features
__device__ float g_y1[(size_t)NTOK * TWOH];              // kan1 output
__device__ float g_WA[240 * IN_F];                       // packed [f0_Wih ; b0_Wih]
__device__ float g_bA[240];                              // packed [f0_bih ; b0_bih]
__device__ float g_Wp1[TWOH * KEXP];                     // packed kan1 weights
__device__ float g_Wp2[IN_F * KEXP];                     // packed kan2 weights

// ---------------- helpers ----------------
__device__ __forceinline__ float sigm_acc(float x) { return 1.0f / (1.0f + expf(-x)); }

// ---------------- weight packing ----------------
__global__ void pack_weights(const float* __restrict__ f0W, const float* __restrict__ b0W,
                             const float* __restrict__ f0b, const float* __restrict__ b0b,
                             const float* __restrict__ k1b, const float* __restrict__ k1s,
                             const float* __restrict__ k1c,
                             const float* __restrict__ k2b, const float* __restrict__ k2s,
                             const float* __restrict__ k2c)
{
    const int NWA  = 240 * IN_F;        // 61680
    const int NBA  = 240;
    const int NW1  = TWOH * KEXP;       // 57600
    const int NW2  = IN_F * KEXP;       // 185040
    int idx = blockIdx.x * blockDim.x + threadIdx.x;
    int total = NWA + NBA + NW1 + NW2;
    if (idx >= total) return;
    if (idx < NWA) {
        int r = idx / IN_F, c = idx % IN_F;
        g_WA[idx] = (r < G3H) ? f0W[r * IN_F + c] : b0W[(r - G3H) * IN_F + c];
        return;
    }
    idx -= NWA;
    if (idx < NBA) {
        g_bA[idx] = (idx < G3H) ? f0b[idx] : b0b[idx - G3H];
        return;
    }
    idx -= NBA;
    if (idx < NW1) {
        int o = idx / KEXP, k = idx % KEXP;
        if (k < TWOH) g_Wp1[idx] = k1b[o * TWOH + k];
        else {
            int e = k - TWOH, i = e >> 3, g = e & 7;
            g_Wp1[idx] = k1s[(o * TWOH + i) * 8 + g] * k1c[o * TWOH + i];
        }
        return;
    }
    idx -= NW1;
    {
        int o = idx / KEXP, k = idx % KEXP;
        if (k < TWOH) g_Wp2[idx] = k2b[o * TWOH + k];
        else {
            int e = k - TWOH, i = e >> 3, g = e & 7;
            g_Wp2[idx] = k2s[(o * TWOH + i) * 8 + g] * k2c[o * TWOH + i];
        }
    }
}

// ---------------- generic NT GEMM: C[n,m] = sum_k A[n,k]*B[m,k] (+bias, +epilogue) ----------------
// EPI 0: plain   EPI 1: scatter to g_giF/g_giB (gates)   EPI 2: 1.2*sigmoid(slope*v)
#define BMg 64
#define BNg 64
#define BKg 16

template <int EPI>
__global__ __launch_bounds__(256) void gemm_nt(
    const float* __restrict__ A, const float* __restrict__ B,
    const float* __restrict__ bias, float* __restrict__ C, float* __restrict__ C2,
    int N, int M, int K, const float* __restrict__ slope)
{
    __shared__ __align__(16) float As[BKg][BMg];
    __shared__ __align__(16) float Bs[BKg][BNg];

    const int tid  = threadIdx.x;
    const int rowT = blockIdx.x * BMg;
    const int colT = blockIdx.y * BNg;
    const int ty = tid >> 4;        // 0..15
    const int tx = tid & 15;        // 0..15
    const int lr = tid >> 2;        // 0..63
    const int lk = (tid & 3) * 4;   // 0,4,8,12

    float acc[4][4];
#pragma unroll
    for (int i = 0; i < 4; i++)
#pragma unroll
        for (int j = 0; j < 4; j++) acc[i][j] = 0.0f;

    for (int k0 = 0; k0 < K; k0 += BKg) {
#pragma unroll
        for (int i = 0; i < 4; i++) {
            int k = k0 + lk + i;
            As[lk + i][lr] = (k < K) ? A[(size_t)(rowT + lr) * K + k] : 0.0f;
            Bs[lk + i][lr] = (k < K && (colT + lr) < M) ? B[(size_t)(colT + lr) * K + k] : 0.0f;
        }
        __syncthreads();
#pragma unroll
        for (int k = 0; k < BKg; k++) {
            float4 a  = *(const float4*)&As[k][ty * 4];
            float4 bv = *(const float4*)&Bs[k][tx * 4];
            float av[4] = {a.x, a.y, a.z, a.w};
            float bb[4] = {bv.x, bv.y, bv.z, bv.w};
#pragma unroll
            for (int i = 0; i < 4; i++)
#pragma unroll
                for (int j = 0; j < 4; j++) acc[i][j] += av[i] * bb[j];
        }
        __syncthreads();
    }

#pragma unroll
    for (int i = 0; i < 4; i++) {
        int row = rowT + ty * 4 + i;
        if (row >= N) continue;
#pragma unroll
        for (int j = 0; j < 4; j++) {
            int col = colT + tx * 4 + j;
            if (col >= M) continue;
            float v = acc[i][j] + (bias ? bias[col] : 0.0f);
            if (EPI == 0) {
                C[(size_t)row * M + col] = v;
            } else if (EPI == 1) {
                int bb_ = row / T_STEPS, tt = row % T_STEPS;
                size_t o = ((size_t)tt * BATCH + bb_) * G3H;
                if (col < G3H) C[o + col] = v;
                else           C2[o + col - G3H] = v;
            } else {
                C[(size_t)row * M + col] = 1.2f / (1.0f + expf(-slope[col] * v));
            }
        }
    }
}

// ---------------- GRU scan: grid (64, 2) = (batch, dir), 256 threads ----------------
__global__ __launch_bounds__(256) void gru_scan(
    const float* __restrict__ WhhF0, const float* __restrict__ bhhF0,
    const float* __restrict__ WihF1, const float* __restrict__ WhhF1,
    const float* __restrict__ bihF1, const float* __restrict__ bhhF1,
    const float* __restrict__ WhhB0, const float* __restrict__ bhhB0,
    const float* __restrict__ WihB1, const float* __restrict__ WhhB1,
    const float* __restrict__ bihB1, const float* __restrict__ bhhB1)
{
    const int b   = blockIdx.x;
    const int dir = blockIdx.y;
    const float* Whh0 = dir ? WhhB0 : WhhF0;
    const float* bhh0 = dir ? bhhB0 : bhhF0;
    const float* W1ih = dir ? WihB1 : WihF1;
    const float* W1hh = dir ? WhhB1 : WhhF1;
    const float* b1ih = dir ? bihB1 : bihF1;
    const float* b1hh = dir ? bhhB1 : bhhF1;
    const float* gi   = dir ? g_giB : g_giF;
    float* out = g_hcat + (size_t)b * T_STEPS * TWOH + dir * HID;

    __shared__ __align__(16) float s_h0[HID];
    __shared__ __align__(16) float s_h1[HID];
    __shared__ float s_gh0[G3H], s_gh1[G3H], s_gi0[G3H], s_gi1[G3H];

    const int tid = threadIdx.x;
    if (tid < HID) { s_h0[tid] = 0.0f; s_h1[tid] = 0.0f; }

    float w0[HID];
    float wa[HID], wb[HID];
    float bias0 = 0.0f, biasA = 0.0f, biasB = 0.0f;
    if (tid < G3H) {
#pragma unroll
        for (int k = 0; k < HID; k++) w0[k] = Whh0[tid * HID + k];
        bias0 = bhh0[tid];
    } else if (tid >= 128 && tid < 128 + G3H) {
        int j = tid - 128;
#pragma unroll
        for (int k = 0; k < HID; k++) { wa[k] = W1hh[j * HID + k]; wb[k] = W1ih[j * HID + k]; }
        biasA = b1hh[j];
        biasB = b1ih[j];
    }
    __syncthreads();

    for (int t = 0; t < T_STEPS; t++) {
        // P1: layer0 recurrent gates + layer1 recurrent gates (independent), prefetch gi0
        if (tid < G3H) {
            int grow = dir ? (T_STEPS - 1 - t) : t;
            s_gi0[tid] = gi[((size_t)grow * BATCH + b) * G3H + tid];
            float acc = bias0;
            const float4* h4 = (const float4*)s_h0;
#pragma unroll
            for (int k = 0; k < HID / 4; k++) {
                float4 h = h4[k];
                acc += h.x * w0[4 * k] + h.y * w0[4 * k + 1] + h.z * w0[4 * k + 2] + h.w * w0[4 * k + 3];
            }
            s_gh0[tid] = acc;
        } else if (tid >= 128 && tid < 128 + G3H) {
            int j = tid - 128;
            float acc = biasA;
            const float4* h4 = (const float4*)s_h1;
#pragma unroll
            for (int k = 0; k < HID / 4; k++) {
                float4 h = h4[k];
                acc += h.x * wa[4 * k] + h.y * wa[4 * k + 1] + h.z * wa[4 * k + 2] + h.w * wa[4 * k + 3];
            }
            s_gh1[j] = acc;
        }
        __syncthreads();
        // P2: h0 update
        if (tid < HID) {
            float r = sigm_acc(s_gi0[tid] + s_gh0[tid]);
            float z = sigm_acc(s_gi0[HID + tid] + s_gh0[HID + tid]);
            float n = tanhf(s_gi0[2 * HID + tid] + r * s_gh0[2 * HID + tid]);
            s_h0[tid] = (1.0f - z) * n + z * s_h0[tid];
        }
        __syncthreads();
        // P3: layer1 input gates from fresh h0
        if (tid >= 128 && tid < 128 + G3H) {
            int j = tid - 128;
            float acc = biasB;
            const float4* h4 = (const float4*)s_h0;
#pragma unroll
            for (int k = 0; k < HID / 4; k++) {
                float4 h = h4[k];
                acc += h.x * wb[4 * k] + h.y * wb[4 * k + 1] + h.z * wb[4 * k + 2] + h.w * wb[4 * k + 3];
            }
            s_gi1[j] = acc;
        }
        __syncthreads();
        // P4: h1 update + store
        if (tid < HID) {
            float r = sigm_acc(s_gi1[tid] + s_gh1[tid]);
            float z = sigm_acc(s_gi1[HID + tid] + s_gh1[HID + tid]);
            float n = tanhf(s_gi1[2 * HID + tid] + r * s_gh1[2 * HID + tid]);
            float h = (1.0f - z) * n + z * s_h1[tid];
            s_h1[tid] = h;
            out[(size_t)t * TWOH + tid] = h;
        }
        __syncthreads();
    }
}

// ---------------- KAN feature expansion: silu + cubic B-spline bases (uniform grid) ----------------
__device__ __forceinline__ float gridv(int j) { return 0.4f * (float)(j - 3) - 1.0f; }

__global__ void expand_feat(const float* __restrict__ X, int total)
{
    int idx = blockIdx.x * blockDim.x + threadIdx.x;
    if (idx >= total) return;
    int n = idx / TWOH;
    int i = idx % TWOH;
    float x = X[idx];

    // silu
    g_feat[(size_t)n * KEXP + i] = x / (1.0f + expf(-x));

    // order-0 bases on 11 intervals
    float bset[11];
#pragma unroll
    for (int j = 0; j < 11; j++)
        bset[j] = (x >= gridv(j) && x < gridv(j + 1)) ? 1.0f : 0.0f;
    // k = 1 (denom 0.4)
#pragma unroll
    for (int j = 0; j < 10; j++)
        bset[j] = (x - gridv(j)) * 2.5f * bset[j] + (gridv(j + 2) - x) * 2.5f * bset[j + 1];
    // k = 2 (denom 0.8)
#pragma unroll
    for (int j = 0; j < 9; j++)
        bset[j] = (x - gridv(j)) * 1.25f * bset[j] + (gridv(j + 3) - x) * 1.25f * bset[j + 1];
    // k = 3 (denom 1.2)
#pragma unroll
    for (int j = 0; j < 8; j++)
        bset[j] = (x - gridv(j)) * (1.0f / 1.2f) * bset[j] + (gridv(j + 4) - x) * (1.0f / 1.2f) * bset[j + 1];

    float4* o = (float4*)&g_feat[(size_t)n * KEXP + TWOH + i * 8];
    o[0] = make_float4(bset[0], bset[1], bset[2], bset[3]);
    o[1] = make_float4(bset[4], bset[5], bset[6], bset[7]);
}

// ---------------- launch ----------------
extern "C" void kernel_launch(void* const* d_in, const int* in_sizes, int n_in,
                              void* d_out, int out_size)
{
    const float* x     = (const float*)d_in[0];
    // d_in[1] = lengths (unused, matches reference)
    const float* f0Wih = (const float*)d_in[2];
    const float* f0Whh = (const float*)d_in[3];
    const float* f0bih = (const float*)d_in[4];
    const float* f0bhh = (const float*)d_in[5];
    const float* f1Wih = (const float*)d_in[6];
    const float* f1Whh = (const float*)d_in[7];
    const float* f1bih = (const float*)d_in[8];
    const float* f1bhh = (const float*)d_in[9];
    const float* b0Wih = (const float*)d_in[10];
    const float* b0Whh = (const float*)d_in[11];
    const float* b0bih = (const float*)d_in[12];
    const float* b0bhh = (const float*)d_in[13];
    const float* b1Wih = (const float*)d_in[14];
    const float* b1Whh = (const float*)d_in[15];
    const float* b1bih = (const float*)d_in[16];
    const float* b1bhh = (const float*)d_in[17];
    const float* k1b   = (const float*)d_in[18];
    const float* k1s   = (const float*)d_in[19];
    const float* k1c   = (const float*)d_in[20];
    const float* k2b   = (const float*)d_in[21];
    const float* k2s   = (const float*)d_in[22];
    const float* k2c   = (const float*)d_in[23];
    const float* slope = (const float*)d_in[24];
    float* out = (float*)d_out;

    float *p_giF, *p_giB, *p_hcat, *p_feat, *p_y1, *p_WA, *p_bA, *p_Wp1, *p_Wp2;
    cudaGetSymbolAddress((void**)&p_giF, g_giF);
    cudaGetSymbolAddress((void**)&p_giB, g_giB);
    cudaGetSymbolAddress((void**)&p_hcat, g_hcat);
    cudaGetSymbolAddress((void**)&p_feat, g_feat);
    cudaGetSymbolAddress((void**)&p_y1, g_y1);
    cudaGetSymbolAddress((void**)&p_WA, g_WA);
    cudaGetSymbolAddress((void**)&p_bA, g_bA);
    cudaGetSymbolAddress((void**)&p_Wp1, g_Wp1);
    cudaGetSymbolAddress((void**)&p_Wp2, g_Wp2);

    // 1. pack weights
    {
        int total = 240 * IN_F + 240 + TWOH * KEXP + IN_F * KEXP;
        pack_weights<<<(total + 255) / 256, 256>>>(f0Wih, b0Wih, f0bih, b0bih,
                                                   k1b, k1s, k1c, k2b, k2s, k2c);
    }
    // 2. layer-0 input gates for both directions: (38400 x 257) @ (240 x 257)^T
    {
        dim3 grid(NTOK / BMg, (240 + BNg - 1) / BNg);
        gemm_nt<1><<<grid, 256>>>(x, p_WA, p_bA, p_giF, p_giB, NTOK, 240, IN_F, nullptr);
    }
    // 3. bidirectional 2-layer GRU scan
    {
        dim3 grid(BATCH, 2);
        gru_scan<<<grid, 256>>>(f0Whh, f0bhh, f1Wih, f1Whh, f1bih, f1bhh,
                                b0Whh, b0bhh, b1Wih, b1Whh, b1bih, b1bhh);
    }
    // 4. KAN layer 1: expand + GEMM
    {
        int total = NTOK * TWOH;
        expand_feat<<<(total + 255) / 256, 256>>>(p_hcat, total);
        dim3 grid(NTOK / BMg, (TWOH + BNg - 1) / BNg);
        gemm_nt<0><<<grid, 256>>>(p_feat, p_Wp1, nullptr, p_y1, nullptr, NTOK, TWOH, KEXP, nullptr);
    }
    // 5. KAN layer 2: expand + GEMM + 1.2*sigmoid(slope*·)
    {
        int total = NTOK * TWOH;
        expand_feat<<<(total + 255) / 256, 256>>>(p_y1, total);
        dim3 grid(NTOK / BMg, (IN_F + BNg - 1) / BNg);
        gemm_nt<2><<<grid, 256>>>(p_feat, p_Wp2, nullptr, out, nullptr, NTOK, IN_F, KEXP, slope);
    }
    (void)in_sizes; (void)n_in; (void)out_size;
}